// round 10
// baseline (speedup 1.0000x reference)
#include <cuda_runtime.h>
#include <stdint.h>

#define TT 256
#define BB 64
#define HH 512
#define RC_CTAS 128
#define NSTG 8         // A-ring stages
#define PFD 6          // prefetch distance

typedef unsigned long long ull;

// -------- scratch (__device__ globals) --------
static __device__ float g_gx[(size_t)8 * TT * BB * HH];      // [dg][t][b][h]
static __device__ float g_out0[(size_t)TT * BB * 2 * HH];    // [t][b][2H]
static __device__ float g_gates[2 * 8 * HH * BB];            // [par][dg][h][b]
static __device__ float g_A[2 * 8 * HH * BB];                // [par][dg][k][b]
static __device__ float g_noiseT[8 * HH * BB];               // [dg][h][b]
static __device__ float g_h[2 * HH * BB];                    // [d][h][b]
static __device__ float g_c[2 * HH * BB];                    // [d][h][b]
// dataflow flags (monotonic step stamps)
static __device__ unsigned g_avail[2][4];    // [d][chunk-group of 8]
static __device__ unsigned g_gflag[8][16];   // [dg][nt]
static __device__ unsigned g_consume[2];     // [d]

#define PAR_STRIDE (8 * HH * BB)

// -------------------- helpers --------------------
__device__ __forceinline__ void ffma2(ull& d, ull a, ull b) {
    asm("fma.rn.f32x2 %0, %1, %2, %0;" : "+l"(d) : "l"(a), "l"(b));
}
__device__ __forceinline__ float2 unpack2(ull v) {
    float2 r;
    asm("mov.b64 {%0, %1}, %2;" : "=f"(r.x), "=f"(r.y) : "l"(v));
    return r;
}
__device__ __forceinline__ void cp_async16(uint32_t s, const void* g) {
    asm volatile("cp.async.ca.shared.global [%0], [%1], 16;" :: "r"(s), "l"(g));
}
__device__ __forceinline__ float fsig(float x) {
    return __fdividef(1.f, 1.f + __expf(-x));
}
__device__ __forceinline__ float ftanh(float x) {
    return 2.f * fsig(2.f * x) - 1.f;
}
__device__ __forceinline__ void mma_tf32(float* d, const uint32_t* a, const uint32_t* b) {
    asm volatile(
        "mma.sync.aligned.m16n8k8.row.col.f32.tf32.tf32.f32 "
        "{%0,%1,%2,%3}, {%4,%5,%6,%7}, {%8,%9}, {%0,%1,%2,%3};"
        : "+f"(d[0]), "+f"(d[1]), "+f"(d[2]), "+f"(d[3])
        : "r"(a[0]), "r"(a[1]), "r"(a[2]), "r"(a[3]), "r"(b[0]), "r"(b[1]));
}
__device__ __forceinline__ float2 tf32_split(float a) {
    uint32_t hb;
    asm("cvt.rna.tf32.f32 %0, %1;" : "=r"(hb) : "f"(a));
    float hi = __uint_as_float(hb);
    return make_float2(hi, a - hi);
}
// flag primitives
__device__ __forceinline__ unsigned ld_flag(const unsigned* p) {
    unsigned v;
    asm volatile("ld.relaxed.gpu.global.u32 %0, [%1];" : "=r"(v) : "l"(p) : "memory");
    return v;
}
__device__ __forceinline__ void fence_acq() {
    asm volatile("fence.acq_rel.gpu;" ::: "memory");
}
__device__ __forceinline__ void flag_add(unsigned* p) {
    asm volatile("red.release.gpu.global.add.u32 [%0], %1;" :: "l"(p), "r"(1u) : "memory");
}

// -------------------- init: zero A + flags (stream-ordered) ------------
__global__ void init_flags_kernel() {
    int i = blockIdx.x * blockDim.x + threadIdx.x;
    for (int j = i; j < 2 * PAR_STRIDE; j += gridDim.x * blockDim.x)
        g_A[j] = 0.f;
    if (i < 8) { g_avail[i >> 2][i & 3] = 0; }
    if (i < 128) g_gflag[i >> 4][i & 15] = 0;
    if (i < 2) g_consume[i] = 0;
}

// -------------------- noise transpose: [dg][b][h] -> [dg][h][b] ---------
__global__ void noiseT_kernel(const float* __restrict__ nh) {
    __shared__ float tile[32][33];
    int dg = blockIdx.z;
    int h0 = blockIdx.x * 32, b0 = blockIdx.y * 32;
    int x = threadIdx.x, y = threadIdx.y;
    #pragma unroll
    for (int i = 0; i < 32; i += 8)
        tile[y + i][x] = nh[(size_t)dg * BB * HH + (size_t)(b0 + y + i) * HH + h0 + x];
    __syncthreads();
    #pragma unroll
    for (int i = 0; i < 32; i += 8)
        g_noiseT[(size_t)dg * HH * BB + (size_t)(h0 + y + i) * BB + b0 + x] = tile[x][y + i];
}

// -------------------- gx GEMM: 3xTF32 (unchanged from R8) --------------
template<int K>
__global__ __launch_bounds__(128)
void gx_gemm_kernel(const float* __restrict__ X,
                    const float* __restrict__ Noise,
                    const float* __restrict__ W,
                    const float* __restrict__ bih,
                    const float* __restrict__ bhh)
{
    const int dg = blockIdx.z;
    const int mt = blockIdx.y;
    const int nt = blockIdx.x;
    const int tid = threadIdx.x;

    __shared__ __align__(16) float2 As[2][64][22];
    __shared__ __align__(16) float2 Bs[2][16][72];

    const float* Xbase = (K == 1024) ? (const float*)g_out0 : X;
    const float* Xp = Xbase + (size_t)mt * BB * K;
    const float* Np = Noise + (size_t)dg * BB * K;
    const float* Wp = W + (size_t)dg * K * HH + nt * 64;

    const int a_lm = tid >> 2;
    const int a_lk = (tid & 3) * 4;
    const int b_lk = tid >> 4;
    const int b_ln = (tid & 15) * 4;

    const int wid = tid >> 5;
    const int wm = wid >> 1;
    const int wn = wid & 1;
    const int lane = tid & 31;
    const int r = lane >> 2;
    const int c = lane & 3;

    float acc[2][4][4];
    #pragma unroll
    for (int i = 0; i < 2; i++)
        #pragma unroll
        for (int j = 0; j < 4; j++)
            #pragma unroll
            for (int q = 0; q < 4; q++) acc[i][j][q] = 0.f;

    float4 xv0, xv1, nv0, nv1, wv0, wv1;
    auto ldg_chunk = [&](int k0) {
        xv0 = *reinterpret_cast<const float4*>(Xp + (size_t)a_lm * K + k0 + a_lk);
        nv0 = *reinterpret_cast<const float4*>(Np + (size_t)a_lm * K + k0 + a_lk);
        xv1 = *reinterpret_cast<const float4*>(Xp + (size_t)(a_lm + 32) * K + k0 + a_lk);
        nv1 = *reinterpret_cast<const float4*>(Np + (size_t)(a_lm + 32) * K + k0 + a_lk);
        wv0 = *reinterpret_cast<const float4*>(Wp + (size_t)(k0 + b_lk) * HH + b_ln);
        wv1 = *reinterpret_cast<const float4*>(Wp + (size_t)(k0 + b_lk + 8) * HH + b_ln);
    };
    auto sts_chunk = [&](int buf) {
        As[buf][a_lm][a_lk + 0] = tf32_split(xv0.x * nv0.x);
        As[buf][a_lm][a_lk + 1] = tf32_split(xv0.y * nv0.y);
        As[buf][a_lm][a_lk + 2] = tf32_split(xv0.z * nv0.z);
        As[buf][a_lm][a_lk + 3] = tf32_split(xv0.w * nv0.w);
        As[buf][a_lm + 32][a_lk + 0] = tf32_split(xv1.x * nv1.x);
        As[buf][a_lm + 32][a_lk + 1] = tf32_split(xv1.y * nv1.y);
        As[buf][a_lm + 32][a_lk + 2] = tf32_split(xv1.z * nv1.z);
        As[buf][a_lm + 32][a_lk + 3] = tf32_split(xv1.w * nv1.w);
        Bs[buf][b_lk][b_ln + 0] = tf32_split(wv0.x);
        Bs[buf][b_lk][b_ln + 1] = tf32_split(wv0.y);
        Bs[buf][b_lk][b_ln + 2] = tf32_split(wv0.z);
        Bs[buf][b_lk][b_ln + 3] = tf32_split(wv0.w);
        Bs[buf][b_lk + 8][b_ln + 0] = tf32_split(wv1.x);
        Bs[buf][b_lk + 8][b_ln + 1] = tf32_split(wv1.y);
        Bs[buf][b_lk + 8][b_ln + 2] = tf32_split(wv1.z);
        Bs[buf][b_lk + 8][b_ln + 3] = tf32_split(wv1.w);
    };

    const int NC = K / 16;
    ldg_chunk(0);
    sts_chunk(0);
    __syncthreads();

    #pragma unroll 1
    for (int ch = 0; ch < NC; ++ch) {
        if (ch + 1 < NC) ldg_chunk((ch + 1) * 16);

        const int cur = ch & 1;
        #pragma unroll
        for (int ks = 0; ks < 2; ks++) {
            const int kb = ks * 8;
            uint32_t ah[2][4], al[2][4];
            #pragma unroll
            for (int mt2 = 0; mt2 < 2; mt2++) {
                const int mb = wm * 32 + mt2 * 16;
                float2 f0 = As[cur][mb + r][kb + c];
                float2 f1 = As[cur][mb + r + 8][kb + c];
                float2 f2 = As[cur][mb + r][kb + c + 4];
                float2 f3 = As[cur][mb + r + 8][kb + c + 4];
                ah[mt2][0] = __float_as_uint(f0.x); al[mt2][0] = __float_as_uint(f0.y);
                ah[mt2][1] = __float_as_uint(f1.x); al[mt2][1] = __float_as_uint(f1.y);
                ah[mt2][2] = __float_as_uint(f2.x); al[mt2][2] = __float_as_uint(f2.y);
                ah[mt2][3] = __float_as_uint(f3.x); al[mt2][3] = __float_as_uint(f3.y);
            }
            uint32_t bh[4][2], bl[4][2];
            #pragma unroll
            for (int n2 = 0; n2 < 4; n2++) {
                const int nb = wn * 32 + n2 * 8 + r;
                float2 f0 = Bs[cur][kb + c][nb];
                float2 f1 = Bs[cur][kb + c + 4][nb];
                bh[n2][0] = __float_as_uint(f0.x); bl[n2][0] = __float_as_uint(f0.y);
                bh[n2][1] = __float_as_uint(f1.x); bl[n2][1] = __float_as_uint(f1.y);
            }
            #pragma unroll
            for (int mt2 = 0; mt2 < 2; mt2++)
                #pragma unroll
                for (int n2 = 0; n2 < 4; n2++) {
                    mma_tf32(acc[mt2][n2], ah[mt2], bl[n2]);
                    mma_tf32(acc[mt2][n2], al[mt2], bh[n2]);
                    mma_tf32(acc[mt2][n2], ah[mt2], bh[n2]);
                }
        }

        if (ch + 1 < NC) {
            sts_chunk((ch + 1) & 1);
            __syncthreads();
        }
    }

    float* Cp = g_gx + ((size_t)dg * TT + mt) * BB * HH;
    #pragma unroll
    for (int mt2 = 0; mt2 < 2; mt2++) {
        #pragma unroll
        for (int n2 = 0; n2 < 4; n2++) {
            const int b0 = wm * 32 + mt2 * 16 + r;
            const int h0 = nt * 64 + wn * 32 + n2 * 8 + 2 * c;
            float bx = bih[dg * HH + h0]     + bhh[dg * HH + h0];
            float by = bih[dg * HH + h0 + 1] + bhh[dg * HH + h0 + 1];
            *reinterpret_cast<float2*>(Cp + (size_t)b0 * HH + h0) =
                make_float2(acc[mt2][n2][0] + bx, acc[mt2][n2][1] + by);
            *reinterpret_cast<float2*>(Cp + (size_t)(b0 + 8) * HH + h0) =
                make_float2(acc[mt2][n2][2] + bx, acc[mt2][n2][3] + by);
        }
    }
}

// -------------------- persistent recurrence: barrier-free dataflow -----
// CTA: dg = cta>>4, nt = cta&15 (GEMM role); slice = cta&63 (pointwise role).
// Double-buffered A and gates (step parity). Flags gate all cross-CTA deps.
__global__ __launch_bounds__(256, 1)
void recur_kernel(const float* __restrict__ Whh,
                  const float* __restrict__ mask,
                  float* __restrict__ outp,
                  int layer,
                  float* __restrict__ hn,
                  float* __restrict__ cn)
{
    extern __shared__ __align__(16) float smem_dyn[];
    float* Ws    = smem_dyn;            // 32768 floats (128KB) duplicated W
    float* Aring = smem_dyn + 32768;    // NSTG*1024 floats

    const int cta = blockIdx.x;
    const int dg  = cta >> 4;
    const int d   = dg >> 2;
    const int nt  = cta & 15;
    const int tid = threadIdx.x;
    const int slice = cta & 63;          // pointwise h-slice

    float* op = (layer == 0) ? (float*)g_out0 : outp;

    // ---- load W slice duplicated
    {
        const float* Wp = Whh + (size_t)dg * HH * HH + nt * 32;
        for (int i = tid; i < 512 * 8; i += 256) {
            int k = i >> 3;
            int c4 = (i & 7) * 4;
            float4 w = *reinterpret_cast<const float4*>(Wp + (size_t)k * HH + c4);
            *reinterpret_cast<float4*>(&Ws[k * 64 + c4 * 2])     = make_float4(w.x, w.x, w.y, w.y);
            *reinterpret_cast<float4*>(&Ws[k * 64 + c4 * 2 + 4]) = make_float4(w.z, w.z, w.w, w.w);
        }
    }
    // ---- zero own h/c slice (private to this CTA)
    for (int i = tid; i < 512; i += 256) { g_h[cta * 512 + i] = 0.f; g_c[cta * 512 + i] = 0.f; }
    __syncthreads();

    const int tc = ((tid >> 5) & 1) * 8 + (tid & 7);
    const int tm = (((tid >> 6) << 2) + ((tid >> 3) & 3)) * 4;
    const uint32_t ar_u32 = (uint32_t)__cvta_generic_to_shared(Aring);
    const float* wsp = Ws + tc * 4;
    unsigned* availd = g_avail[d];

    for (int step = 0; step < TT; ++step) {
        const int t = (d == 0) ? step : (TT - 1 - step);

        // gx prefetch (DRAM, hidden behind GEMM)
        const float* gxp = g_gx + ((size_t)dg * TT + t) * BB * HH;
        const int c0 = nt * 32 + tc * 2;
        float2 gxb[4];
        #pragma unroll
        for (int p = 0; p < 4; p++)
            gxb[p] = *reinterpret_cast<const float2*>(gxp + (size_t)(tm + p) * HH + c0);

        const float* Abase = g_A + (size_t)(step & 1) * PAR_STRIDE + (size_t)dg * HH * BB;

        // ---- wait for group 0 of A(step), prime pipeline ----
        if (tid == 0) {
            while (ld_flag(&availd[0]) < 16u * (unsigned)step) {}
            fence_acq();
        }
        __syncthreads();
        #pragma unroll
        for (int p = 0; p < PFD; p++) {
            cp_async16(ar_u32 + (uint32_t)p * 4096 + tid * 16,
                       Abase + (size_t)p * 1024 + tid * 4);
            asm volatile("cp.async.commit_group;");
        }

        ull a00 = 0, a01 = 0, a10 = 0, a11 = 0;
        int slot = 0, wslot = PFD;
        #pragma unroll 1
        for (int ch = 0; ch < 32; ++ch) {
            const int c2 = ch + PFD;
            if (tid == 0 && c2 < 32 && (c2 & 7) == 0) {
                while (ld_flag(&availd[c2 >> 3]) < 16u * (unsigned)step) {}
                fence_acq();
            }
            asm volatile("cp.async.wait_group %0;" :: "n"(PFD - 1));
            __syncthreads();

            const float* asr = Aring + slot * 1024;
            if (++slot == NSTG) slot = 0;
            #pragma unroll
            for (int kk = 0; kk < 16; kk++) {
                ulonglong2 a2 = *reinterpret_cast<const ulonglong2*>(asr + kk * 64 + tm);
                ulonglong2 w2 = *reinterpret_cast<const ulonglong2*>(
                    wsp + (size_t)(ch * 16 + kk) * 64);
                ffma2(a00, a2.x, w2.x);
                ffma2(a01, a2.y, w2.x);
                ffma2(a10, a2.x, w2.y);
                ffma2(a11, a2.y, w2.y);
            }

            if (c2 < 32)
                cp_async16(ar_u32 + (uint32_t)wslot * 4096 + tid * 16,
                           Abase + (size_t)c2 * 1024 + tid * 4);
            if (++wslot == NSTG) wslot = 0;
            asm volatile("cp.async.commit_group;");
        }

        // ---- epilogue: gates(step) -> parity buffer ----
        {
            float* gbase = g_gates + (size_t)(step & 1) * PAR_STRIDE;
            float2 u00 = unpack2(a00), u01 = unpack2(a01);
            float2 u10 = unpack2(a10), u11 = unpack2(a11);
            float4 v0 = make_float4(u00.x + gxb[0].x, u00.y + gxb[1].x,
                                    u01.x + gxb[2].x, u01.y + gxb[3].x);
            float4 v1 = make_float4(u10.x + gxb[0].y, u10.y + gxb[1].y,
                                    u11.x + gxb[2].y, u11.y + gxb[3].y);
            *reinterpret_cast<float4*>(gbase + ((size_t)dg * HH + c0) * BB + tm) = v0;
            *reinterpret_cast<float4*>(gbase + ((size_t)dg * HH + c0 + 1) * BB + tm) = v1;
        }
        __syncthreads();
        if (tid == 0) {
            flag_add(&g_gflag[dg][nt]);     // gates(step) cols ready
            flag_add(&g_consume[d]);        // A(step) consumed by this CTA
        }

        // ---- pointwise: wait gate cols (4 CTAs) + A-buffer free ----
        if (tid == 0) {
            const int ntp = slice >> 2;
            const unsigned need = (unsigned)step + 1u;
            while (ld_flag(&g_gflag[d * 4 + 0][ntp]) < need) {}
            while (ld_flag(&g_gflag[d * 4 + 1][ntp]) < need) {}
            while (ld_flag(&g_gflag[d * 4 + 2][ntp]) < need) {}
            while (ld_flag(&g_gflag[d * 4 + 3][ntp]) < need) {}
            while (ld_flag(&g_consume[d]) < 64u * (unsigned)step) {}
            fence_acq();
        }
        __syncthreads();

        {
            int idx = cta * 512 + tid * 2;
            int rem = idx & 32767;
            int h   = rem >> 6;
            int b   = rem & 63;

            const float* gb = g_gates + (size_t)(step & 1) * PAR_STRIDE +
                              ((size_t)d * 4 * HH + h) * BB + b;
            float2 gi = *reinterpret_cast<const float2*>(gb);
            float2 gf = *reinterpret_cast<const float2*>(gb + (size_t)HH * BB);
            float2 gg = *reinterpret_cast<const float2*>(gb + (size_t)2 * HH * BB);
            float2 go = *reinterpret_cast<const float2*>(gb + (size_t)3 * HH * BB);

            int sidx = (d * HH + h) * BB + b;
            float2 cp = *reinterpret_cast<float2*>(&g_c[sidx]);
            float2 hp = *reinterpret_cast<float2*>(&g_h[sidx]);
            float2 mt = *reinterpret_cast<const float2*>(mask + t * BB + b);

            float2 hm, cm;
            {
                float cnew = fsig(gf.x) * cp.x + fsig(gi.x) * ftanh(gg.x);
                float hnew = fsig(go.x) * ftanh(cnew);
                hm.x = hnew * mt.x + hp.x * (1.f - mt.x);
                cm.x = cnew * mt.x + cp.x * (1.f - mt.x);
            }
            {
                float cnew = fsig(gf.y) * cp.y + fsig(gi.y) * ftanh(gg.y);
                float hnew = fsig(go.y) * ftanh(cnew);
                hm.y = hnew * mt.y + hp.y * (1.f - mt.y);
                cm.y = cnew * mt.y + cp.y * (1.f - mt.y);
            }

            *reinterpret_cast<float2*>(&g_h[sidx]) = hm;
            *reinterpret_cast<float2*>(&g_c[sidx]) = cm;

            // A(step+1) into parity buffer (step+1)&1
            float* Anext = g_A + (size_t)((step + 1) & 1) * PAR_STRIDE;
            #pragma unroll
            for (int g = 0; g < 4; g++) {
                int ai = (((d * 4 + g) * HH) + h) * BB + b;
                float2 nz = *reinterpret_cast<const float2*>(&g_noiseT[ai]);
                *reinterpret_cast<float2*>(&Anext[ai]) = make_float2(hm.x * nz.x, hm.y * nz.y);
            }

            size_t ob = (size_t)t * BB * 2 * HH + (size_t)b * 2 * HH + d * HH + h;
            op[ob] = hm.x;
            op[ob + 2 * HH] = hm.y;

            if (step == TT - 1) {
                size_t oi = ((size_t)(layer * 2 + d) * BB + b) * HH + h;
                hn[oi] = hm.x; hn[oi + HH] = hm.y;
                cn[oi] = cm.x; cn[oi + HH] = cm.y;
            }
        }
        __syncthreads();
        if (tid == 0) flag_add(&availd[slice >> 4]);   // A(step+1) rows published
    }
}

// -------------------- launch --------------------
extern "C" void kernel_launch(void* const* d_in, const int* in_sizes, int n_in,
                              void* d_out, int out_size)
{
    const float* x      = (const float*)d_in[0];
    const float* mask   = (const float*)d_in[1];
    const float* w_ih0  = (const float*)d_in[2];
    const float* w_hh0  = (const float*)d_in[3];
    const float* b_ih0  = (const float*)d_in[4];
    const float* b_hh0  = (const float*)d_in[5];
    const float* n_in0  = (const float*)d_in[6];
    const float* n_hid0 = (const float*)d_in[7];
    const float* w_ih1  = (const float*)d_in[8];
    const float* w_hh1  = (const float*)d_in[9];
    const float* b_ih1  = (const float*)d_in[10];
    const float* b_hh1  = (const float*)d_in[11];
    const float* n_in1  = (const float*)d_in[12];
    const float* n_hid1 = (const float*)d_in[13];

    float* out  = (float*)d_out;
    float* hn   = out + (size_t)TT * BB * 2 * HH;
    float* cn   = hn + (size_t)4 * BB * HH;

    const int recur_smem = 131072 + NSTG * 4096;
    static bool attr_set = false;
    if (!attr_set) {
        cudaFuncSetAttribute(recur_kernel,
                             cudaFuncAttributeMaxDynamicSharedMemorySize, recur_smem);
        attr_set = true;
    }

    dim3 gxgrid(HH / 64, TT, 8);
    dim3 ntgrid(16, 2, 8);
    dim3 ntblk(32, 8);

    // layer 0
    noiseT_kernel<<<ntgrid, ntblk>>>(n_hid0);
    gx_gemm_kernel<512><<<gxgrid, 128>>>(x, n_in0, w_ih0, b_ih0, b_hh0);
    init_flags_kernel<<<256, 256>>>();
    recur_kernel<<<RC_CTAS, 256, recur_smem>>>(w_hh0, mask, out, 0, hn, cn);

    // layer 1
    noiseT_kernel<<<ntgrid, ntblk>>>(n_hid1);
    gx_gemm_kernel<1024><<<gxgrid, 128>>>(nullptr, n_in1, w_ih1, b_ih1, b_hh1);
    init_flags_kernel<<<256, 256>>>();
    recur_kernel<<<RC_CTAS, 256, recur_smem>>>(w_hh1, mask, out, 1, hn, cn);
}

// round 12
// speedup vs baseline: 1.2221x; 1.2221x over previous
#include <cuda_runtime.h>
#include <cuda_bf16.h>
#include <stdint.h>

#define TT 256
#define BB 64
#define HH 512
#define RC_CTAS 128
#define NSTG 3
#define PFD 2

typedef unsigned long long ull;

// -------- scratch (__device__ globals) --------
static __device__ float g_gx[(size_t)8 * TT * BB * HH];      // [dg][t][b][h]
static __device__ float g_out0[(size_t)TT * BB * 2 * HH];    // [t][b][2H]
static __device__ float g_gates[8 * HH * BB];                // [dg][h][b]
static __device__ float g_A[8 * HH * BB];                    // [dg][k][b]
static __device__ float g_noiseT[8 * HH * BB];               // [dg][h][b]
static __device__ float g_h[2 * HH * BB];                    // [d][h][b]
static __device__ float g_c[2 * HH * BB];                    // [d][h][b]
static __device__ unsigned g_bar_count;
static __device__ unsigned g_bar_gen;

// -------------------- helpers --------------------
__device__ __forceinline__ void ffma2(ull& d, ull a, ull b) {
    asm("fma.rn.f32x2 %0, %1, %2, %0;" : "+l"(d) : "l"(a), "l"(b));
}
__device__ __forceinline__ float2 unpack2(ull v) {
    float2 r;
    asm("mov.b64 {%0, %1}, %2;" : "=f"(r.x), "=f"(r.y) : "l"(v));
    return r;
}
__device__ __forceinline__ void cp_async16(uint32_t s, const void* g) {
    asm volatile("cp.async.ca.shared.global [%0], [%1], 16;" :: "r"(s), "l"(g));
}
__device__ __forceinline__ float fsig(float x) {
    return __fdividef(1.f, 1.f + __expf(-x));
}
__device__ __forceinline__ float ftanh(float x) {
    return 2.f * fsig(2.f * x) - 1.f;
}
__device__ __forceinline__ void mma_bf16(float* d, const uint32_t* a, const uint32_t* b) {
    asm volatile(
        "mma.sync.aligned.m16n8k16.row.col.f32.bf16.bf16.f32 "
        "{%0,%1,%2,%3}, {%4,%5,%6,%7}, {%8,%9}, {%0,%1,%2,%3};"
        : "+f"(d[0]), "+f"(d[1]), "+f"(d[2]), "+f"(d[3])
        : "r"(a[0]), "r"(a[1]), "r"(a[2]), "r"(a[3]), "r"(b[0]), "r"(b[1]));
}
// bf16 Dekker split: hi = bf16(a), lo = bf16(a - hi)
__device__ __forceinline__ void bsplit(float a, uint16_t& h, uint16_t& l) {
    __nv_bfloat16 bh = __float2bfloat16(a);
    float r = a - __bfloat162float(bh);
    __nv_bfloat16 bl = __float2bfloat16(r);
    h = *reinterpret_cast<uint16_t*>(&bh);
    l = *reinterpret_cast<uint16_t*>(&bl);
}
__device__ __forceinline__ uint32_t pack2(uint16_t lo, uint16_t hi) {
    return (uint32_t)lo | ((uint32_t)hi << 16);
}

// -------------------- barrier reset (stream-ordered) --------------------
__global__ void zero_bar_kernel() {
    g_bar_count = 0;
    g_bar_gen = 0;
}

// -------------------- noise transpose: [dg][b][h] -> [dg][h][b] ---------
__global__ void noiseT_kernel(const float* __restrict__ nh) {
    __shared__ float tile[32][33];
    int dg = blockIdx.z;
    int h0 = blockIdx.x * 32, b0 = blockIdx.y * 32;
    int x = threadIdx.x, y = threadIdx.y;
    #pragma unroll
    for (int i = 0; i < 32; i += 8)
        tile[y + i][x] = nh[(size_t)dg * BB * HH + (size_t)(b0 + y + i) * HH + h0 + x];
    __syncthreads();
    #pragma unroll
    for (int i = 0; i < 32; i += 8)
        g_noiseT[(size_t)dg * HH * BB + (size_t)(h0 + y + i) * BB + b0 + x] = tile[x][y + i];
}

// -------------------- gx GEMM v5: bf16x3 tensor-core --------------------
// C[t*B+b][h] = sum_k X[t,b,k]*Noise[dg,b,k]*W[dg,k,h] + (b_ih+b_hh)
// 64x64x16 tiles, 128 threads (2x2 warps, m32xn32/warp).
// Operands split hi/lo bf16; D += Ah*Bh + Ah*Bl + Al*Bh (m16n8k16).
template<int K>
__global__ __launch_bounds__(128)
void gx_gemm_kernel(const float* __restrict__ X,
                    const float* __restrict__ Noise,
                    const float* __restrict__ W,
                    const float* __restrict__ bih,
                    const float* __restrict__ bhh)
{
    const int dg = blockIdx.z;
    const int mt = blockIdx.y;
    const int nt = blockIdx.x;
    const int tid = threadIdx.x;

    // A: [m=64][kpair=8] packed bf16x2, pad 12 -> conflict-free frag loads
    __shared__ uint32_t Ah[2][64][12];
    __shared__ uint32_t Al[2][64][12];
    // B: [kpair=8][n=64] packed bf16x2 (lo=even k, hi=odd k), pad 72
    __shared__ uint32_t Bhs[2][8][72];
    __shared__ uint32_t Bls[2][8][72];

    const float* Xbase = (K == 1024) ? (const float*)g_out0 : X;
    const float* Xp = Xbase + (size_t)mt * BB * K;
    const float* Np = Noise + (size_t)dg * BB * K;
    const float* Wp = W + (size_t)dg * K * HH + nt * 64;

    // staging indices
    const int a_lm = tid >> 2;          // 0..31 (rows; +32 second half)
    const int a_c  = tid & 3;           // k group: k = 4c..4c+3, kpairs 2c,2c+1
    const int b_kp = tid >> 4;          // 0..7 kpair -> k rows 2kp, 2kp+1
    const int b_ln = (tid & 15) * 4;    // 0..60

    // warp decomposition
    const int wid = tid >> 5;
    const int wm = wid >> 1;
    const int wn = wid & 1;
    const int lane = tid & 31;
    const int gid = lane >> 2;          // 0..7
    const int t4 = lane & 3;            // 0..3

    float acc[2][4][4];
    #pragma unroll
    for (int i = 0; i < 2; i++)
        #pragma unroll
        for (int j = 0; j < 4; j++)
            #pragma unroll
            for (int q = 0; q < 4; q++) acc[i][j][q] = 0.f;

    float4 xv0, xv1, nv0, nv1, wv0, wv1;
    auto ldg_chunk = [&](int k0) {
        xv0 = *reinterpret_cast<const float4*>(Xp + (size_t)a_lm * K + k0 + a_c * 4);
        nv0 = *reinterpret_cast<const float4*>(Np + (size_t)a_lm * K + k0 + a_c * 4);
        xv1 = *reinterpret_cast<const float4*>(Xp + (size_t)(a_lm + 32) * K + k0 + a_c * 4);
        nv1 = *reinterpret_cast<const float4*>(Np + (size_t)(a_lm + 32) * K + k0 + a_c * 4);
        wv0 = *reinterpret_cast<const float4*>(Wp + (size_t)(k0 + 2 * b_kp) * HH + b_ln);
        wv1 = *reinterpret_cast<const float4*>(Wp + (size_t)(k0 + 2 * b_kp + 1) * HH + b_ln);
    };
    auto sts_chunk = [&](int buf) {
        float p[4];
        uint16_t ph[4], pl[4];
        // A row a_lm
        p[0] = xv0.x * nv0.x; p[1] = xv0.y * nv0.y; p[2] = xv0.z * nv0.z; p[3] = xv0.w * nv0.w;
        #pragma unroll
        for (int i = 0; i < 4; i++) bsplit(p[i], ph[i], pl[i]);
        Ah[buf][a_lm][2 * a_c]     = pack2(ph[0], ph[1]);
        Ah[buf][a_lm][2 * a_c + 1] = pack2(ph[2], ph[3]);
        Al[buf][a_lm][2 * a_c]     = pack2(pl[0], pl[1]);
        Al[buf][a_lm][2 * a_c + 1] = pack2(pl[2], pl[3]);
        // A row a_lm+32
        p[0] = xv1.x * nv1.x; p[1] = xv1.y * nv1.y; p[2] = xv1.z * nv1.z; p[3] = xv1.w * nv1.w;
        #pragma unroll
        for (int i = 0; i < 4; i++) bsplit(p[i], ph[i], pl[i]);
        Ah[buf][a_lm + 32][2 * a_c]     = pack2(ph[0], ph[1]);
        Ah[buf][a_lm + 32][2 * a_c + 1] = pack2(ph[2], ph[3]);
        Al[buf][a_lm + 32][2 * a_c]     = pack2(pl[0], pl[1]);
        Al[buf][a_lm + 32][2 * a_c + 1] = pack2(pl[2], pl[3]);
        // B: pack (k even, k odd) per n
        float w0[4] = {wv0.x, wv0.y, wv0.z, wv0.w};
        float w1[4] = {wv1.x, wv1.y, wv1.z, wv1.w};
        #pragma unroll
        for (int j = 0; j < 4; j++) {
            uint16_t h0, l0, h1, l1;
            bsplit(w0[j], h0, l0);
            bsplit(w1[j], h1, l1);
            Bhs[buf][b_kp][b_ln + j] = pack2(h0, h1);
            Bls[buf][b_kp][b_ln + j] = pack2(l0, l1);
        }
    };

    const int NC = K / 16;
    ldg_chunk(0);
    sts_chunk(0);
    __syncthreads();

    #pragma unroll 1
    for (int ch = 0; ch < NC; ++ch) {
        if (ch + 1 < NC) ldg_chunk((ch + 1) * 16);

        const int cur = ch & 1;
        // A fragments (hi/lo), 2 m-tiles
        uint32_t aH[2][4], aL[2][4];
        #pragma unroll
        for (int mt2 = 0; mt2 < 2; mt2++) {
            const int r0 = wm * 32 + mt2 * 16 + gid;
            const int r1 = r0 + 8;
            aH[mt2][0] = Ah[cur][r0][t4];
            aH[mt2][1] = Ah[cur][r1][t4];
            aH[mt2][2] = Ah[cur][r0][t4 + 4];
            aH[mt2][3] = Ah[cur][r1][t4 + 4];
            aL[mt2][0] = Al[cur][r0][t4];
            aL[mt2][1] = Al[cur][r1][t4];
            aL[mt2][2] = Al[cur][r0][t4 + 4];
            aL[mt2][3] = Al[cur][r1][t4 + 4];
        }
        // B fragments (hi/lo), 4 n-tiles
        uint32_t bH[4][2], bL[4][2];
        #pragma unroll
        for (int n2 = 0; n2 < 4; n2++) {
            const int nb = wn * 32 + n2 * 8 + gid;
            bH[n2][0] = Bhs[cur][t4][nb];
            bH[n2][1] = Bhs[cur][t4 + 4][nb];
            bL[n2][0] = Bls[cur][t4][nb];
            bL[n2][1] = Bls[cur][t4 + 4][nb];
        }
        #pragma unroll
        for (int mt2 = 0; mt2 < 2; mt2++)
            #pragma unroll
            for (int n2 = 0; n2 < 4; n2++) {
                mma_bf16(acc[mt2][n2], aH[mt2], bH[n2]);
                mma_bf16(acc[mt2][n2], aH[mt2], bL[n2]);
                mma_bf16(acc[mt2][n2], aL[mt2], bH[n2]);
            }

        if (ch + 1 < NC) {
            sts_chunk((ch + 1) & 1);
            __syncthreads();
        }
    }

    // epilogue: D[b][h] + bias -> g_gx[dg][t][b][h]
    float* Cp = g_gx + ((size_t)dg * TT + mt) * BB * HH;
    #pragma unroll
    for (int mt2 = 0; mt2 < 2; mt2++) {
        #pragma unroll
        for (int n2 = 0; n2 < 4; n2++) {
            const int b0 = wm * 32 + mt2 * 16 + gid;
            const int h0 = nt * 64 + wn * 32 + n2 * 8 + 2 * t4;
            float bx = bih[dg * HH + h0]     + bhh[dg * HH + h0];
            float by = bih[dg * HH + h0 + 1] + bhh[dg * HH + h0 + 1];
            *reinterpret_cast<float2*>(Cp + (size_t)b0 * HH + h0) =
                make_float2(acc[mt2][n2][0] + bx, acc[mt2][n2][1] + by);
            *reinterpret_cast<float2*>(Cp + (size_t)(b0 + 8) * HH + h0) =
                make_float2(acc[mt2][n2][2] + bx, acc[mt2][n2][3] + by);
        }
    }
}

// -------------------- persistent recurrence (verbatim R8 best) ----------
__global__ __launch_bounds__(256, 1)
void recur_kernel(const float* __restrict__ Whh,
                  const float* __restrict__ mask,
                  float* __restrict__ outp,
                  int layer,
                  float* __restrict__ hn,
                  float* __restrict__ cn)
{
    extern __shared__ float Ws[];                    // [512][64] duplicated = 128KB
    __shared__ __align__(16) float Asb[3][16][64];   // 12KB, 3-stage ring

    const int cta = blockIdx.x;
    const int dg  = cta >> 4;
    const int d   = dg >> 2;
    const int nt  = cta & 15;
    const int tid = threadIdx.x;

    float* op = (layer == 0) ? (float*)g_out0 : outp;

    {
        const float* Wp = Whh + (size_t)dg * HH * HH + nt * 32;
        for (int i = tid; i < 512 * 8; i += 256) {
            int k = i >> 3;
            int c4 = (i & 7) * 4;
            float4 w = *reinterpret_cast<const float4*>(Wp + (size_t)k * HH + c4);
            *reinterpret_cast<float4*>(&Ws[k * 64 + c4 * 2])     = make_float4(w.x, w.x, w.y, w.y);
            *reinterpret_cast<float4*>(&Ws[k * 64 + c4 * 2 + 4]) = make_float4(w.z, w.z, w.w, w.w);
        }
    }
    for (int i = tid; i < 512; i += 256) { g_h[cta * 512 + i] = 0.f; g_c[cta * 512 + i] = 0.f; }
    for (int i = tid; i < 2048; i += 256) g_A[cta * 2048 + i] = 0.f;

    unsigned bar_n = 0;
    auto grid_bar = [&]() {
        __syncthreads();
        ++bar_n;
        if (tid == 0) {
            asm volatile("red.release.gpu.global.add.u32 [%0], %1;"
                         :: "l"(&g_bar_count), "r"(1u) : "memory");
            if (cta == 0) {
                unsigned c;
                do {
                    asm volatile("ld.acquire.gpu.global.u32 %0, [%1];"
                                 : "=r"(c) : "l"(&g_bar_count) : "memory");
                } while (c < bar_n * RC_CTAS);
                asm volatile("st.release.gpu.global.u32 [%0], %1;"
                             :: "l"(&g_bar_gen), "r"(bar_n) : "memory");
            } else {
                unsigned gv;
                do {
                    asm volatile("ld.acquire.gpu.global.u32 %0, [%1];"
                                 : "=r"(gv) : "l"(&g_bar_gen) : "memory");
                } while (gv < bar_n);
            }
        }
        __syncthreads();
    };

    grid_bar();

    const int tc = ((tid >> 5) & 1) * 8 + (tid & 7);
    const int tm = (((tid >> 6) << 2) + ((tid >> 3) & 3)) * 4;
    const float* Abase = g_A + (size_t)dg * HH * BB;
    const uint32_t as_u32 = (uint32_t)__cvta_generic_to_shared(&Asb[0][0][0]);
    const float* wsp = Ws + tc * 4;

    for (int step = 0; step < TT; ++step) {
        const int t = (d == 0) ? step : (TT - 1 - step);

        const float* gxp = g_gx + ((size_t)dg * TT + t) * BB * HH;
        const int c0 = nt * 32 + tc * 2;
        float2 gxb[4];
        #pragma unroll
        for (int p = 0; p < 4; p++)
            gxb[p] = *reinterpret_cast<const float2*>(gxp + (size_t)(tm + p) * HH + c0);

        cp_async16(as_u32 + 0 * 4096 + tid * 16, Abase + 0 * 1024 + tid * 4);
        asm volatile("cp.async.commit_group;");
        cp_async16(as_u32 + 1 * 4096 + tid * 16, Abase + 1 * 1024 + tid * 4);
        asm volatile("cp.async.commit_group;");

        ull a00 = 0, a01 = 0, a10 = 0, a11 = 0;
        #pragma unroll 1
        for (int ch = 0; ch < 32; ++ch) {
            asm volatile("cp.async.wait_group 1;");
            __syncthreads();

            const float* asr = &Asb[0][0][0] + (ch % 3) * 1024;
            #pragma unroll
            for (int kk = 0; kk < 16; kk++) {
                ulonglong2 a2 = *reinterpret_cast<const ulonglong2*>(asr + kk * 64 + tm);
                ulonglong2 w2 = *reinterpret_cast<const ulonglong2*>(
                    wsp + (size_t)(ch * 16 + kk) * 64);
                ffma2(a00, a2.x, w2.x);
                ffma2(a01, a2.y, w2.x);
                ffma2(a10, a2.x, w2.y);
                ffma2(a11, a2.y, w2.y);
            }

            if (ch + 2 < 32)
                cp_async16(as_u32 + ((ch + 2) % 3) * 4096 + tid * 16,
                           Abase + (size_t)(ch + 2) * 1024 + tid * 4);
            asm volatile("cp.async.commit_group;");
        }

        {
            float2 u00 = unpack2(a00), u01 = unpack2(a01);
            float2 u10 = unpack2(a10), u11 = unpack2(a11);
            float4 v0 = make_float4(u00.x + gxb[0].x, u00.y + gxb[1].x,
                                    u01.x + gxb[2].x, u01.y + gxb[3].x);
            float4 v1 = make_float4(u10.x + gxb[0].y, u10.y + gxb[1].y,
                                    u11.x + gxb[2].y, u11.y + gxb[3].y);
            *reinterpret_cast<float4*>(g_gates + ((size_t)dg * HH + c0) * BB + tm) = v0;
            *reinterpret_cast<float4*>(g_gates + ((size_t)dg * HH + c0 + 1) * BB + tm) = v1;
        }

        grid_bar();

        {
            int idx = cta * 512 + tid * 2;
            int d2  = idx >> 15;
            int rem = idx & 32767;
            int h   = rem >> 6;
            int b   = rem & 63;
            int t2  = (d2 == 0) ? step : (TT - 1 - step);

            const float* gb = g_gates + ((size_t)d2 * 4 * HH + h) * BB + b;
            float2 gi = *reinterpret_cast<const float2*>(gb);
            float2 gf = *reinterpret_cast<const float2*>(gb + (size_t)HH * BB);
            float2 gg = *reinterpret_cast<const float2*>(gb + (size_t)2 * HH * BB);
            float2 go = *reinterpret_cast<const float2*>(gb + (size_t)3 * HH * BB);

            int sidx = (d2 * HH + h) * BB + b;
            float2 cp = *reinterpret_cast<float2*>(&g_c[sidx]);
            float2 hp = *reinterpret_cast<float2*>(&g_h[sidx]);
            float2 mt = *reinterpret_cast<const float2*>(mask + t2 * BB + b);

            float2 hm, cm;
            {
                float cnew = fsig(gf.x) * cp.x + fsig(gi.x) * ftanh(gg.x);
                float hnew = fsig(go.x) * ftanh(cnew);
                hm.x = hnew * mt.x + hp.x * (1.f - mt.x);
                cm.x = cnew * mt.x + cp.x * (1.f - mt.x);
            }
            {
                float cnew = fsig(gf.y) * cp.y + fsig(gi.y) * ftanh(gg.y);
                float hnew = fsig(go.y) * ftanh(cnew);
                hm.y = hnew * mt.y + hp.y * (1.f - mt.y);
                cm.y = cnew * mt.y + cp.y * (1.f - mt.y);
            }

            *reinterpret_cast<float2*>(&g_h[sidx]) = hm;
            *reinterpret_cast<float2*>(&g_c[sidx]) = cm;

            #pragma unroll
            for (int g = 0; g < 4; g++) {
                int ai = (((d2 * 4 + g) * HH) + h) * BB + b;
                float2 nz = *reinterpret_cast<const float2*>(&g_noiseT[ai]);
                *reinterpret_cast<float2*>(&g_A[ai]) = make_float2(hm.x * nz.x, hm.y * nz.y);
            }

            size_t ob = (size_t)t2 * BB * 2 * HH + (size_t)b * 2 * HH + d2 * HH + h;
            op[ob] = hm.x;
            op[ob + 2 * HH] = hm.y;

            if (step == TT - 1) {
                size_t oi = ((size_t)(layer * 2 + d2) * BB + b) * HH + h;
                hn[oi] = hm.x; hn[oi + HH] = hm.y;
                cn[oi] = cm.x; cn[oi + HH] = cm.y;
            }
        }

        grid_bar();
    }
}

// -------------------- launch --------------------
extern "C" void kernel_launch(void* const* d_in, const int* in_sizes, int n_in,
                              void* d_out, int out_size)
{
    const float* x      = (const float*)d_in[0];
    const float* mask   = (const float*)d_in[1];
    const float* w_ih0  = (const float*)d_in[2];
    const float* w_hh0  = (const float*)d_in[3];
    const float* b_ih0  = (const float*)d_in[4];
    const float* b_hh0  = (const float*)d_in[5];
    const float* n_in0  = (const float*)d_in[6];
    const float* n_hid0 = (const float*)d_in[7];
    const float* w_ih1  = (const float*)d_in[8];
    const float* w_hh1  = (const float*)d_in[9];
    const float* b_ih1  = (const float*)d_in[10];
    const float* b_hh1  = (const float*)d_in[11];
    const float* n_in1  = (const float*)d_in[12];
    const float* n_hid1 = (const float*)d_in[13];

    float* out  = (float*)d_out;
    float* hn   = out + (size_t)TT * BB * 2 * HH;
    float* cn   = hn + (size_t)4 * BB * HH;

    static bool attr_set = false;
    if (!attr_set) {
        cudaFuncSetAttribute(recur_kernel,
                             cudaFuncAttributeMaxDynamicSharedMemorySize, 131072);
        attr_set = true;
    }

    dim3 gxgrid(HH / 64, TT, 8);
    dim3 ntgrid(16, 2, 8);
    dim3 ntblk(32, 8);

    // layer 0
    noiseT_kernel<<<ntgrid, ntblk>>>(n_hid0);
    gx_gemm_kernel<512><<<gxgrid, 128>>>(x, n_in0, w_ih0, b_ih0, b_hh0);
    zero_bar_kernel<<<1, 1>>>();
    recur_kernel<<<RC_CTAS, 256, 131072>>>(w_hh0, mask, out, 0, hn, cn);

    // layer 1
    noiseT_kernel<<<ntgrid, ntblk>>>(n_hid1);
    gx_gemm_kernel<1024><<<gxgrid, 128>>>(nullptr, n_in1, w_ih1, b_ih1, b_hh1);
    zero_bar_kernel<<<1, 1>>>();
    recur_kernel<<<RC_CTAS, 256, 131072>>>(w_hh1, mask, out, 1, hn, cn);
}

// round 13
// speedup vs baseline: 1.7327x; 1.4178x over previous
#include <cuda_runtime.h>
#include <cuda_bf16.h>
#include <stdint.h>

#define TT 256
#define BB 64
#define HH 512
#define RC_CTAS 128

typedef unsigned long long ull;

// -------- scratch (__device__ globals) --------
static __device__ float g_gx[(size_t)8 * TT * BB * HH];      // [dg][t][b][h]
static __device__ float g_out0[(size_t)TT * BB * 2 * HH];    // [t][b][2H]
static __device__ float g_gates[8 * BB * HH];                // [dg][b][h]
static __device__ uint32_t g_Ah[8 * BB * 256];               // [dg][b][kpair] bf16x2 hi
static __device__ uint32_t g_Al[8 * BB * 256];               // [dg][b][kpair] bf16x2 lo
static __device__ unsigned g_bar_count;
static __device__ unsigned g_bar_gen;

// -------------------- helpers --------------------
__device__ __forceinline__ void cp_async16(uint32_t s, const void* g) {
    asm volatile("cp.async.ca.shared.global [%0], [%1], 16;" :: "r"(s), "l"(g));
}
__device__ __forceinline__ float fsig(float x) {
    return __fdividef(1.f, 1.f + __expf(-x));
}
__device__ __forceinline__ float ftanh(float x) {
    return 2.f * fsig(2.f * x) - 1.f;
}
__device__ __forceinline__ void mma_bf16(float* d, const uint32_t* a, const uint32_t* b) {
    asm volatile(
        "mma.sync.aligned.m16n8k16.row.col.f32.bf16.bf16.f32 "
        "{%0,%1,%2,%3}, {%4,%5,%6,%7}, {%8,%9}, {%0,%1,%2,%3};"
        : "+f"(d[0]), "+f"(d[1]), "+f"(d[2]), "+f"(d[3])
        : "r"(a[0]), "r"(a[1]), "r"(a[2]), "r"(a[3]), "r"(b[0]), "r"(b[1]));
}
__device__ __forceinline__ void bsplit(float a, uint16_t& h, uint16_t& l) {
    __nv_bfloat16 bh = __float2bfloat16(a);
    float r = a - __bfloat162float(bh);
    __nv_bfloat16 bl = __float2bfloat16(r);
    h = *reinterpret_cast<uint16_t*>(&bh);
    l = *reinterpret_cast<uint16_t*>(&bl);
}
__device__ __forceinline__ uint32_t pack2(uint16_t lo, uint16_t hi) {
    return (uint32_t)lo | ((uint32_t)hi << 16);
}

// -------------------- barrier reset --------------------
__global__ void zero_bar_kernel() {
    g_bar_count = 0;
    g_bar_gen = 0;
}

// -------------------- gx GEMM: bf16x3 (verbatim R12) --------------------
template<int K>
__global__ __launch_bounds__(128)
void gx_gemm_kernel(const float* __restrict__ X,
                    const float* __restrict__ Noise,
                    const float* __restrict__ W,
                    const float* __restrict__ bih,
                    const float* __restrict__ bhh)
{
    const int dg = blockIdx.z;
    const int mt = blockIdx.y;
    const int nt = blockIdx.x;
    const int tid = threadIdx.x;

    __shared__ uint32_t Ah[2][64][12];
    __shared__ uint32_t Al[2][64][12];
    __shared__ uint32_t Bhs[2][8][72];
    __shared__ uint32_t Bls[2][8][72];

    const float* Xbase = (K == 1024) ? (const float*)g_out0 : X;
    const float* Xp = Xbase + (size_t)mt * BB * K;
    const float* Np = Noise + (size_t)dg * BB * K;
    const float* Wp = W + (size_t)dg * K * HH + nt * 64;

    const int a_lm = tid >> 2;
    const int a_c  = tid & 3;
    const int b_kp = tid >> 4;
    const int b_ln = (tid & 15) * 4;

    const int wid = tid >> 5;
    const int wm = wid >> 1;
    const int wn = wid & 1;
    const int lane = tid & 31;
    const int gid = lane >> 2;
    const int t4 = lane & 3;

    float acc[2][4][4];
    #pragma unroll
    for (int i = 0; i < 2; i++)
        #pragma unroll
        for (int j = 0; j < 4; j++)
            #pragma unroll
            for (int q = 0; q < 4; q++) acc[i][j][q] = 0.f;

    float4 xv0, xv1, nv0, nv1, wv0, wv1;
    auto ldg_chunk = [&](int k0) {
        xv0 = *reinterpret_cast<const float4*>(Xp + (size_t)a_lm * K + k0 + a_c * 4);
        nv0 = *reinterpret_cast<const float4*>(Np + (size_t)a_lm * K + k0 + a_c * 4);
        xv1 = *reinterpret_cast<const float4*>(Xp + (size_t)(a_lm + 32) * K + k0 + a_c * 4);
        nv1 = *reinterpret_cast<const float4*>(Np + (size_t)(a_lm + 32) * K + k0 + a_c * 4);
        wv0 = *reinterpret_cast<const float4*>(Wp + (size_t)(k0 + 2 * b_kp) * HH + b_ln);
        wv1 = *reinterpret_cast<const float4*>(Wp + (size_t)(k0 + 2 * b_kp + 1) * HH + b_ln);
    };
    auto sts_chunk = [&](int buf) {
        float p[4];
        uint16_t ph[4], pl[4];
        p[0] = xv0.x * nv0.x; p[1] = xv0.y * nv0.y; p[2] = xv0.z * nv0.z; p[3] = xv0.w * nv0.w;
        #pragma unroll
        for (int i = 0; i < 4; i++) bsplit(p[i], ph[i], pl[i]);
        Ah[buf][a_lm][2 * a_c]     = pack2(ph[0], ph[1]);
        Ah[buf][a_lm][2 * a_c + 1] = pack2(ph[2], ph[3]);
        Al[buf][a_lm][2 * a_c]     = pack2(pl[0], pl[1]);
        Al[buf][a_lm][2 * a_c + 1] = pack2(pl[2], pl[3]);
        p[0] = xv1.x * nv1.x; p[1] = xv1.y * nv1.y; p[2] = xv1.z * nv1.z; p[3] = xv1.w * nv1.w;
        #pragma unroll
        for (int i = 0; i < 4; i++) bsplit(p[i], ph[i], pl[i]);
        Ah[buf][a_lm + 32][2 * a_c]     = pack2(ph[0], ph[1]);
        Ah[buf][a_lm + 32][2 * a_c + 1] = pack2(ph[2], ph[3]);
        Al[buf][a_lm + 32][2 * a_c]     = pack2(pl[0], pl[1]);
        Al[buf][a_lm + 32][2 * a_c + 1] = pack2(pl[2], pl[3]);
        float w0[4] = {wv0.x, wv0.y, wv0.z, wv0.w};
        float w1[4] = {wv1.x, wv1.y, wv1.z, wv1.w};
        #pragma unroll
        for (int j = 0; j < 4; j++) {
            uint16_t h0, l0, h1, l1;
            bsplit(w0[j], h0, l0);
            bsplit(w1[j], h1, l1);
            Bhs[buf][b_kp][b_ln + j] = pack2(h0, h1);
            Bls[buf][b_kp][b_ln + j] = pack2(l0, l1);
        }
    };

    const int NC = K / 16;
    ldg_chunk(0);
    sts_chunk(0);
    __syncthreads();

    #pragma unroll 1
    for (int ch = 0; ch < NC; ++ch) {
        if (ch + 1 < NC) ldg_chunk((ch + 1) * 16);

        const int cur = ch & 1;
        uint32_t aH[2][4], aL[2][4];
        #pragma unroll
        for (int mt2 = 0; mt2 < 2; mt2++) {
            const int r0 = wm * 32 + mt2 * 16 + gid;
            const int r1 = r0 + 8;
            aH[mt2][0] = Ah[cur][r0][t4];
            aH[mt2][1] = Ah[cur][r1][t4];
            aH[mt2][2] = Ah[cur][r0][t4 + 4];
            aH[mt2][3] = Ah[cur][r1][t4 + 4];
            aL[mt2][0] = Al[cur][r0][t4];
            aL[mt2][1] = Al[cur][r1][t4];
            aL[mt2][2] = Al[cur][r0][t4 + 4];
            aL[mt2][3] = Al[cur][r1][t4 + 4];
        }
        uint32_t bH[4][2], bL[4][2];
        #pragma unroll
        for (int n2 = 0; n2 < 4; n2++) {
            const int nb = wn * 32 + n2 * 8 + gid;
            bH[n2][0] = Bhs[cur][t4][nb];
            bH[n2][1] = Bhs[cur][t4 + 4][nb];
            bL[n2][0] = Bls[cur][t4][nb];
            bL[n2][1] = Bls[cur][t4 + 4][nb];
        }
        #pragma unroll
        for (int mt2 = 0; mt2 < 2; mt2++)
            #pragma unroll
            for (int n2 = 0; n2 < 4; n2++) {
                mma_bf16(acc[mt2][n2], aH[mt2], bH[n2]);
                mma_bf16(acc[mt2][n2], aH[mt2], bL[n2]);
                mma_bf16(acc[mt2][n2], aL[mt2], bH[n2]);
            }

        if (ch + 1 < NC) {
            sts_chunk((ch + 1) & 1);
            __syncthreads();
        }
    }

    float* Cp = g_gx + ((size_t)dg * TT + mt) * BB * HH;
    #pragma unroll
    for (int mt2 = 0; mt2 < 2; mt2++) {
        #pragma unroll
        for (int n2 = 0; n2 < 4; n2++) {
            const int b0 = wm * 32 + mt2 * 16 + gid;
            const int h0 = nt * 64 + wn * 32 + n2 * 8 + 2 * t4;
            float bx = bih[dg * HH + h0]     + bhh[dg * HH + h0];
            float by = bih[dg * HH + h0 + 1] + bhh[dg * HH + h0 + 1];
            *reinterpret_cast<float2*>(Cp + (size_t)b0 * HH + h0) =
                make_float2(acc[mt2][n2][0] + bx, acc[mt2][n2][1] + by);
            *reinterpret_cast<float2*>(Cp + (size_t)(b0 + 8) * HH + h0) =
                make_float2(acc[mt2][n2][2] + bx, acc[mt2][n2][3] + by);
        }
    }
}

// -------------------- persistent recurrence v3: bf16x3 tensor GEMM ------
// GEMM role:     dg = cta>>4, nt = cta&15  -> 32 cols of gate dg, all 64 batches
// pointwise role: d = cta>>6, pb = cta&63  -> all 512 h of one (dir, batch); h/c in regs
// smem: Bh/Bl [256][40] packed W hi/lo (80KB) + A ring [3][hi/lo][64][12] (18KB)
__global__ __launch_bounds__(256, 1)
void recur_kernel(const float* __restrict__ Whh,
                  const float* __restrict__ NoiseH,
                  const float* __restrict__ mask,
                  float* __restrict__ outp,
                  int layer,
                  float* __restrict__ hn,
                  float* __restrict__ cn)
{
    extern __shared__ __align__(16) uint32_t smem_dyn[];
    uint32_t* Bh = smem_dyn;                 // [256][40]
    uint32_t* Bl = Bh + 256 * 40;            // [256][40]
    uint32_t* Ar = Bl + 256 * 40;            // ring: 3 stages x (768 hi + 768 lo)

    const int cta = blockIdx.x;
    const int dg  = cta >> 4;
    const int d   = dg >> 2;                 // == cta>>6
    const int nt  = cta & 15;
    const int pb  = cta & 63;
    const int tid = threadIdx.x;

    float* op = (layer == 0) ? (float*)g_out0 : outp;

    // ---- startup: split W slice into packed bf16x2 hi/lo smem ----
    {
        const float* Wp = Whh + (size_t)dg * HH * HH + nt * 32;
        for (int i = tid; i < 256 * 32; i += 256) {
            int kp = i >> 5;
            int n  = i & 31;
            float w0 = Wp[(size_t)(2 * kp) * HH + n];
            float w1 = Wp[(size_t)(2 * kp + 1) * HH + n];
            uint16_t h0, l0, h1, l1;
            bsplit(w0, h0, l0);
            bsplit(w1, h1, l1);
            Bh[kp * 40 + n] = pack2(h0, h1);
            Bl[kp * 40 + n] = pack2(l0, l1);
        }
    }
    // ---- zero A slice (h0 = 0) ----
    #pragma unroll
    for (int i = 0; i < 4; i++) {
        g_Ah[cta * 1024 + tid + i * 256] = 0;
        g_Al[cta * 1024 + tid + i * 256] = 0;
    }

    // ---- leader-release grid barrier (monotonic; reset by zero_bar) ----
    unsigned bar_n = 0;
    auto grid_bar = [&]() {
        __syncthreads();
        ++bar_n;
        if (tid == 0) {
            asm volatile("red.release.gpu.global.add.u32 [%0], %1;"
                         :: "l"(&g_bar_count), "r"(1u) : "memory");
            if (cta == 0) {
                unsigned c;
                do {
                    asm volatile("ld.acquire.gpu.global.u32 %0, [%1];"
                                 : "=r"(c) : "l"(&g_bar_count) : "memory");
                } while (c < bar_n * RC_CTAS);
                asm volatile("st.release.gpu.global.u32 [%0], %1;"
                             :: "l"(&g_bar_gen), "r"(bar_n) : "memory");
            } else {
                unsigned gv;
                do {
                    asm volatile("ld.acquire.gpu.global.u32 %0, [%1];"
                                 : "=r"(gv) : "l"(&g_bar_gen) : "memory");
                } while (gv < bar_n);
            }
        }
        __syncthreads();
    };

    grid_bar();

    // fragment ids
    const int wid = tid >> 5;
    const int wm = wid >> 1;                 // 0..3 -> m0 = 16*wm
    const int wn = wid & 1;                  // 0..1 -> n-group 16*wn
    const int lane = tid & 31;
    const int gid = lane >> 2;
    const int t4 = lane & 3;
    const int m0 = wm * 16;
    const int n0q = wn * 16;

    // cp.async staging ids
    const int cs_sel  = tid >> 7;            // 0 = hi, 1 = lo
    const int cs_b    = (tid & 127) >> 1;
    const int cs_half = tid & 1;
    const uint32_t ar_u32 = (uint32_t)__cvta_generic_to_shared(Ar);
    const uint32_t* cs_src_base =
        (cs_sel ? g_Al : g_Ah) + ((size_t)dg * BB + cs_b) * 256 + 4 * cs_half;
    const uint32_t cs_dst_off = (uint32_t)(cs_sel * 768 + cs_b * 12 + 4 * cs_half) * 4;

    // pointwise state in registers (h = 2*tid, 2*tid+1 of (d, pb))
    float2 hreg = make_float2(0.f, 0.f);
    float2 creg = make_float2(0.f, 0.f);

    for (int step = 0; step < TT; ++step) {
        const int t = (d == 0) ? step : (TT - 1 - step);

        // gx prefetch for epilogue: gx[dg][t][b][h]
        const float* gxp = g_gx + ((size_t)dg * TT + t) * BB * HH;
        float2 gxb[2][2];
        #pragma unroll
        for (int n2 = 0; n2 < 2; n2++) {
            const int col = nt * 32 + n0q + n2 * 8 + 2 * t4;
            gxb[n2][0] = *reinterpret_cast<const float2*>(gxp + (size_t)(m0 + gid) * HH + col);
            gxb[n2][1] = *reinterpret_cast<const float2*>(gxp + (size_t)(m0 + gid + 8) * HH + col);
        }

        // ---- GEMM: 3-stage cp.async ring over 32 ksteps ----
        cp_async16(ar_u32 + 0 * 6144 + cs_dst_off, cs_src_base + 0 * 8);
        asm volatile("cp.async.commit_group;");
        cp_async16(ar_u32 + 1 * 6144 + cs_dst_off, cs_src_base + 1 * 8);
        asm volatile("cp.async.commit_group;");

        float acc[2][4];
        #pragma unroll
        for (int n2 = 0; n2 < 2; n2++)
            #pragma unroll
            for (int q = 0; q < 4; q++) acc[n2][q] = 0.f;

        #pragma unroll 1
        for (int ch = 0; ch < 32; ++ch) {
            asm volatile("cp.async.wait_group 1;");
            __syncthreads();

            const uint32_t* Ahs = Ar + (ch % 3) * 1536;
            const uint32_t* Als = Ahs + 768;

            uint32_t aH[4], aL[4];
            const int r0 = (m0 + gid) * 12;
            const int r1 = (m0 + gid + 8) * 12;
            aH[0] = Ahs[r0 + t4];
            aH[1] = Ahs[r1 + t4];
            aH[2] = Ahs[r0 + t4 + 4];
            aH[3] = Ahs[r1 + t4 + 4];
            aL[0] = Als[r0 + t4];
            aL[1] = Als[r1 + t4];
            aL[2] = Als[r0 + t4 + 4];
            aL[3] = Als[r1 + t4 + 4];

            const int kprow0 = (8 * ch + t4) * 40;
            const int kprow1 = (8 * ch + t4 + 4) * 40;
            #pragma unroll
            for (int n2 = 0; n2 < 2; n2++) {
                const int bn = n0q + n2 * 8 + gid;
                uint32_t bHf[2], bLf[2];
                bHf[0] = Bh[kprow0 + bn];
                bHf[1] = Bh[kprow1 + bn];
                bLf[0] = Bl[kprow0 + bn];
                bLf[1] = Bl[kprow1 + bn];
                mma_bf16(acc[n2], aH, bHf);
                mma_bf16(acc[n2], aH, bLf);
                mma_bf16(acc[n2], aL, bHf);
            }

            if (ch + 2 < 32)
                cp_async16(ar_u32 + ((ch + 2) % 3) * 6144 + cs_dst_off,
                           cs_src_base + (size_t)(ch + 2) * 8);
            asm volatile("cp.async.commit_group;");
        }

        // ---- epilogue: gates[dg][b][h] = acc + gx ----
        #pragma unroll
        for (int n2 = 0; n2 < 2; n2++) {
            const int col = nt * 32 + n0q + n2 * 8 + 2 * t4;
            *reinterpret_cast<float2*>(g_gates + ((size_t)dg * BB + m0 + gid) * HH + col) =
                make_float2(acc[n2][0] + gxb[n2][0].x, acc[n2][1] + gxb[n2][0].y);
            *reinterpret_cast<float2*>(g_gates + ((size_t)dg * BB + m0 + gid + 8) * HH + col) =
                make_float2(acc[n2][2] + gxb[n2][1].x, acc[n2][3] + gxb[n2][1].y);
        }

        grid_bar();

        // ---- pointwise: (d, pb), h = 2*tid — everything coalesced ----
        {
            const int h = 2 * tid;
            const float* gb = g_gates + ((size_t)(d * 4) * BB + pb) * HH + h;
            const size_t gs = (size_t)BB * HH;
            float2 gi = *reinterpret_cast<const float2*>(gb);
            float2 gf = *reinterpret_cast<const float2*>(gb + gs);
            float2 gg = *reinterpret_cast<const float2*>(gb + 2 * gs);
            float2 go = *reinterpret_cast<const float2*>(gb + 3 * gs);

            const float mt = mask[t * BB + pb];

            float2 hm, cm;
            {
                float cnew = fsig(gf.x) * creg.x + fsig(gi.x) * ftanh(gg.x);
                float hnew = fsig(go.x) * ftanh(cnew);
                hm.x = hnew * mt + hreg.x * (1.f - mt);
                cm.x = cnew * mt + creg.x * (1.f - mt);
            }
            {
                float cnew = fsig(gf.y) * creg.y + fsig(gi.y) * ftanh(gg.y);
                float hnew = fsig(go.y) * ftanh(cnew);
                hm.y = hnew * mt + hreg.y * (1.f - mt);
                cm.y = cnew * mt + creg.y * (1.f - mt);
            }
            hreg = hm; creg = cm;

            // A(step+1) = h*noise, split into packed bf16x2 hi/lo
            #pragma unroll
            for (int g = 0; g < 4; g++) {
                const int dgp = d * 4 + g;
                float2 nz = *reinterpret_cast<const float2*>(
                    NoiseH + ((size_t)dgp * BB + pb) * HH + h);
                float v0 = hm.x * nz.x;
                float v1 = hm.y * nz.y;
                uint16_t h0, l0, h1, l1;
                bsplit(v0, h0, l0);
                bsplit(v1, h1, l1);
                const size_t ai = ((size_t)dgp * BB + pb) * 256 + tid;
                g_Ah[ai] = pack2(h0, h1);
                g_Al[ai] = pack2(l0, l1);
            }

            *reinterpret_cast<float2*>(op + (size_t)t * BB * 2 * HH +
                                       (size_t)pb * 2 * HH + d * HH + h) = hm;

            if (step == TT - 1) {
                const size_t oi = ((size_t)(layer * 2 + d) * BB + pb) * HH + h;
                *reinterpret_cast<float2*>(hn + oi) = hm;
                *reinterpret_cast<float2*>(cn + oi) = cm;
            }
        }

        grid_bar();
    }
}

// -------------------- launch --------------------
extern "C" void kernel_launch(void* const* d_in, const int* in_sizes, int n_in,
                              void* d_out, int out_size)
{
    const float* x      = (const float*)d_in[0];
    const float* mask   = (const float*)d_in[1];
    const float* w_ih0  = (const float*)d_in[2];
    const float* w_hh0  = (const float*)d_in[3];
    const float* b_ih0  = (const float*)d_in[4];
    const float* b_hh0  = (const float*)d_in[5];
    const float* n_in0  = (const float*)d_in[6];
    const float* n_hid0 = (const float*)d_in[7];
    const float* w_ih1  = (const float*)d_in[8];
    const float* w_hh1  = (const float*)d_in[9];
    const float* b_ih1  = (const float*)d_in[10];
    const float* b_hh1  = (const float*)d_in[11];
    const float* n_in1  = (const float*)d_in[12];
    const float* n_hid1 = (const float*)d_in[13];

    float* out  = (float*)d_out;
    float* hn   = out + (size_t)TT * BB * 2 * HH;
    float* cn   = hn + (size_t)4 * BB * HH;

    // smem: Bh/Bl 2*256*40*4 = 81920 B + ring 3*1536*4 = 18432 B
    const int recur_smem = 81920 + 18432;
    static bool attr_set = false;
    if (!attr_set) {
        cudaFuncSetAttribute(recur_kernel,
                             cudaFuncAttributeMaxDynamicSharedMemorySize, recur_smem);
        attr_set = true;
    }

    dim3 gxgrid(HH / 64, TT, 8);

    // layer 0
    gx_gemm_kernel<512><<<gxgrid, 128>>>(x, n_in0, w_ih0, b_ih0, b_hh0);
    zero_bar_kernel<<<1, 1>>>();
    recur_kernel<<<RC_CTAS, 256, recur_smem>>>(w_hh0, n_hid0, mask, out, 0, hn, cn);

    // layer 1
    gx_gemm_kernel<1024><<<gxgrid, 128>>>(nullptr, n_in1, w_ih1, b_ih1, b_hh1);
    zero_bar_kernel<<<1, 1>>>();
    recur_kernel<<<RC_CTAS, 256, recur_smem>>>(w_hh1, n_hid1, mask, out, 1, hn, cn);
}